// round 11
// baseline (speedup 1.0000x reference)
#include <cuda_runtime.h>

#define N 6000
#define NMS_TH 0.7f
#define MAX_E (1 << 20)
#define NCHUNK 12      // rank chunks of 500
#define GC 12          // cells per axis (cell size 16 over [0,192))
#define NCELL (GC*GC*GC)
#define SE_CAP 8000    // shared-memory CSR capacity
#define NW 188         // ceil(6000/32) mask words
#define POST_SMEM_INTS ((N + 1) + N + SE_CAP + SE_CAP + NW + NW)

// ---------------- device scratch ----------------
__device__ int           g_rankpart[NCHUNK * N];
__device__ float4        g_filt[N];              // cx, cy, cz, R2 (rank order)
__device__ float4        g_boxA[N];              // x1, y1, x2, y2 (rank order)
__device__ float4        g_boxB[N];              // z1, z2, area, score (rank order)
__device__ int           g_cellid[N];
__device__ int           g_cellcnt[NCELL];
__device__ int           g_celloff[NCELL + 1];
__device__ float4        g_cfilt[N];             // filter data in cell-list order
__device__ int           g_crank[N];             // rank index in cell-list order
__device__ int           g_rowcnt[N];
__device__ int           g_rowoff[N + 1];
__device__ int           g_fill[N];
__device__ unsigned int  g_eij[MAX_E];           // (i<<16)|j, i<j
__device__ float         g_ev[MAX_E];
__device__ int           g_csrj[MAX_E];
__device__ float         g_csrv[MAX_E];
__device__ int           g_ecount;
__device__ int           g_done;                 // last-block detector for k_scatter
__device__ unsigned int  g_maskw[NW];

// ---------------- K1: partial rank counts, 2 rows per thread + zero counters ----------------
__global__ void k_rank(const float* __restrict__ scores) {
    __shared__ float ss[500];
    int tx = threadIdx.x;
    int j0 = blockIdx.y * 500;
    for (int jj = tx; jj < 500; jj += 256) ss[jj] = scores[j0 + jj];

    if (blockIdx.x == 0 && blockIdx.y == 0) {
        for (int c = tx; c < NCELL; c += 256) g_cellcnt[c] = 0;
        for (int c = tx; c < N; c += 256) g_rowcnt[c] = 0;
        if (tx == 0) { g_ecount = 0; g_done = 0; }
    }
    __syncthreads();

    int i0 = blockIdx.x * 512 + tx;
    int i1 = i0 + 256;
    float s0 = (i0 < N) ? scores[i0] : 0.0f;
    float s1 = (i1 < N) ? scores[i1] : 0.0f;
    int c0 = 0, c1 = 0;
#pragma unroll 5
    for (int jj = 0; jj < 500; jj++) {
        float t = ss[jj];
        int jg = j0 + jj;
        c0 += (t > s0) || (t == s0 && jg < i0);
        c1 += (t > s1) || (t == s1 && jg < i1);
    }
    if (i0 < N) g_rankpart[blockIdx.y * N + i0] = c0;
    if (i1 < N) g_rankpart[blockIdx.y * N + i1] = c1;
}

// ---------------- K2: scatter + cell binning; last block does scan + fill ----------------
__global__ void k_scatter(const float* __restrict__ boxes,
                          const float* __restrict__ scores) {
    int gid = blockIdx.x * 256 + threadIdx.x;
    if (gid < N) {
        int c = 0;
#pragma unroll
        for (int k = 0; k < NCHUNK; k++) c += g_rankpart[k * N + gid];

        float x1 = boxes[gid * 6 + 0], y1 = boxes[gid * 6 + 1];
        float x2 = boxes[gid * 6 + 2], y2 = boxes[gid * 6 + 3];
        float z1 = boxes[gid * 6 + 4], z2 = boxes[gid * 6 + 5];
        float s = scores[gid];
        g_boxA[c] = make_float4(x1, y1, x2, y2);
        g_boxB[c] = make_float4(z1, z2, (x2 - x1) * (y2 - y1) * (z2 - z1), s);
        float cx = (x2 + x1) * 0.5f, cy = (y2 + y1) * 0.5f, cz = (z1 + z2) * 0.5f;
        float rx = (x2 - x1) * 0.5f, ry = (y2 - y1) * 0.5f, rz = (z2 - z1) * 0.5f;
        float R2 = 0.36f * (rx * rx + ry * ry + rz * rz);
        R2 = R2 * 1.002f + 1e-3f;   // margin vs fp rounding (necessary-condition filter)
        g_filt[c] = make_float4(cx, cy, cz, R2);

        int ix = min(GC - 1, max(0, __float2int_rd(cx * 0.0625f)));
        int iy = min(GC - 1, max(0, __float2int_rd(cy * 0.0625f)));
        int iz = min(GC - 1, max(0, __float2int_rd(cz * 0.0625f)));
        int cid = (iz * GC + iy) * GC + ix;
        g_cellid[c] = cid;
        atomicAdd(&g_cellcnt[cid], 1);
    }

    // ---- last-block-done: scan + cell-ordered fill ----
    __threadfence();
    __shared__ int isLast;
    if (threadIdx.x == 0)
        isLast = (atomicAdd(&g_done, 1) == (int)gridDim.x - 1);
    __syncthreads();
    if (!isLast) return;
    __threadfence();   // acquire: make all blocks' writes visible

    __shared__ int wsum[8];
    __shared__ int sfill[NCELL];
    int t = threadIdx.x;          // 256 threads
    // each thread scans 7 cells (7*256 = 1792 >= 1728)
    int cnt7[7];
    int local = 0;
#pragma unroll
    for (int k = 0; k < 7; k++) {
        int idx = t * 7 + k;
        cnt7[k] = (idx < NCELL) ? g_cellcnt[idx] : 0;
        local += cnt7[k];
    }
    int v = local;
#pragma unroll
    for (int o = 1; o < 32; o <<= 1) {
        int u = __shfl_up_sync(0xFFFFFFFFu, v, o);
        if ((t & 31) >= o) v += u;
    }
    if ((t & 31) == 31) wsum[t >> 5] = v;
    __syncthreads();
    if (t < 8) {
        int w = wsum[t];
#pragma unroll
        for (int o = 1; o < 8; o <<= 1) {
            int u = __shfl_up_sync(0xFFu, w, o);
            if (t >= o) w += u;
        }
        wsum[t] = w;
    }
    __syncthreads();
    int run = v - local + ((t >= 32) ? wsum[(t >> 5) - 1] : 0);
#pragma unroll
    for (int k = 0; k < 7; k++) {
        int idx = t * 7 + k;
        if (idx < NCELL) {
            sfill[idx] = run;
            g_celloff[idx] = run;
            run += cnt7[k];
        }
    }
    if (t == 255) g_celloff[NCELL] = run;
    __syncthreads();
    for (int c = t; c < N; c += 256) {
        int cid = g_cellid[c];
        int pos = atomicAdd(&sfill[cid], 1);
        g_crank[pos] = c;
        g_cfilt[pos] = g_filt[c];
    }
}

// ---------------- K3: edge extraction, one warp per (j, z-row) ----------------
// Coverage proof: DIoU>=0.7 => per-dim |dc| <= 0.6*min(halfwidth) <= 13.2 < 16,
// so the 27-cell neighborhood of j's cell contains every qualifying partner.
__global__ void k_edges() {
    int gt = blockIdx.x * 256 + threadIdx.x;
    int task = gt >> 5;
    int lane = gt & 31;
    if (task >= N * 3) return;
    int j = task / 3;
    int dz = task - j * 3 - 1;     // -1, 0, +1

    float4 bf = g_filt[j];
    int czi = min(GC - 1, max(0, __float2int_rd(bf.z * 0.0625f)));
    int zz = czi + dz;
    if (zz < 0 || zz >= GC) return;

    float4 A = g_boxA[j];          // x1,y1,x2,y2
    float4 B = g_boxB[j];          // z1,z2,area,score

    int cxi = min(GC - 1, max(0, __float2int_rd(bf.x * 0.0625f)));
    int cyi = min(GC - 1, max(0, __float2int_rd(bf.y * 0.0625f)));
    int ylo = max(0, cyi - 1), yhi = min(GC - 1, cyi + 1);
    int xlo = max(0, cxi - 1), xhi = min(GC - 1, cxi + 1);

    for (int yy = ylo; yy <= yhi; yy++) {
        int rowbase = (zz * GC + yy) * GC;
        int s = g_celloff[rowbase + xlo];
        int e = g_celloff[rowbase + xhi + 1];   // x-contiguous cells: one span
        for (int p = s + lane; p < e; p += 32) {
            float4 f = g_cfilt[p];              // contiguous per-warp load
            int i = g_crank[p];
            float dx = bf.x - f.x, dy = bf.y - f.y, dz2 = bf.z - f.z;
            float d2 = dx * dx + dy * dy + dz2 * dz2;
            if (i < j && d2 <= fminf(f.w, bf.w)) {
                float4 Ai = g_boxA[i];
                float4 Bi = g_boxB[i];
                float iw = fminf(Ai.z, A.z) - fmaxf(Ai.x, A.x);
                float ih = fminf(Ai.w, A.w) - fmaxf(Ai.y, A.y);
                float dp = fminf(Bi.y, B.y) - fmaxf(Bi.x, B.x);
                if (iw > 0.0f && ih > 0.0f && dp > 0.0f) {
                    float inter = iw * ih * dp;
                    float uni = Bi.z + B.z - inter + 1e-7f;
                    float ow = fmaxf(Ai.z, A.z) - fminf(Ai.x, A.x);
                    float oh = fmaxf(Ai.w, A.w) - fminf(Ai.y, A.y);
                    float od = fmaxf(Bi.y, B.y) - fminf(Bi.x, B.x);
                    float odiag = ow * ow + oh * oh + od * od + 1e-7f;
                    float v = inter / uni - d2 / odiag;
                    if (v >= NMS_TH) {
                        int e2 = atomicAdd(&g_ecount, 1);
                        if (e2 < MAX_E) {
                            g_eij[e2] = ((unsigned)i << 16) | (unsigned)j;
                            g_ev[e2] = v;
                            atomicAdd(&g_rowcnt[i], 1);
                        }
                    }
                }
            }
        }
    }
}

// ---------------- K4: CSR + fixed-point + merge + outputs (1 block, all-shared) ----------------
__global__ void k_post(float* __restrict__ out) {
    extern __shared__ int dyn[];
    int*          srow  = dyn;                      // N+1 row offsets
    int*          sfil  = srow + (N + 1);           // N fill cursors
    int*          scj   = sfil + N;                 // SE_CAP csr j
    float*        scv   = (float*)(scj + SE_CAP);   // SE_CAP csr v
    unsigned int* smask = (unsigned int*)(scv + SE_CAP);
    unsigned int* ssup  = smask + NW;
    __shared__ int wsum[32];
    int t = threadIdx.x;

    // offsets: per-thread chunk of 6 rows, shuffle-based block scan
    int base = t * 6;
    int cnt6[6];
    int local = 0;
#pragma unroll
    for (int k = 0; k < 6; k++) {
        int idx = base + k;
        cnt6[k] = (idx < N) ? g_rowcnt[idx] : 0;
        local += cnt6[k];
    }
    int v = local;
#pragma unroll
    for (int o = 1; o < 32; o <<= 1) {
        int u = __shfl_up_sync(0xFFFFFFFFu, v, o);
        if ((t & 31) >= o) v += u;
    }
    if ((t & 31) == 31) wsum[t >> 5] = v;
    __syncthreads();
    if (t < 32) {
        int w = wsum[t];
#pragma unroll
        for (int o = 1; o < 32; o <<= 1) {
            int u = __shfl_up_sync(0xFFFFFFFFu, w, o);
            if (t >= o) w += u;
        }
        wsum[t] = w;
    }
    __syncthreads();
    int run = v - local + ((t >= 32) ? wsum[(t >> 5) - 1] : 0);
#pragma unroll
    for (int k = 0; k < 6; k++) {
        int idx = base + k;
        if (idx < N) {
            srow[idx] = run;
            sfil[idx] = run;
            run += cnt6[k];
        }
    }
    if (t == 1023) srow[N] = run;
    if (t < NW) smask[t] = 0xFFFFFFFFu;
    __syncthreads();

    int E = g_ecount;
    if (E > MAX_E) E = MAX_E;
    bool shared_path = (E <= SE_CAP);

    int* cj;
    float* cv;
    if (shared_path) {
        cj = scj; cv = scv;
        for (int e = t; e < E; e += 1024) {
            unsigned p = g_eij[e];
            int i = p >> 16;
            int pos = atomicAdd(&sfil[i], 1);
            scj[pos] = (int)(p & 0xFFFF);
            scv[pos] = g_ev[e];
        }
    } else {
        cj = g_csrj; cv = g_csrv;
        for (int e = t; e < E; e += 1024) {
            unsigned p = g_eij[e];
            int i = p >> 16;
            int pos = atomicAdd(&sfil[i], 1);
            g_csrj[pos] = (int)(p & 0xFFFF);
            g_csrv[pos] = g_ev[e];
        }
    }
    __syncthreads();

    // per-row insertion sort by j (determinism)
    for (int i = t; i < N; i += 1024) {
        int s0 = srow[i], s1 = srow[i + 1];
        for (int a = s0 + 1; a < s1; a++) {
            int jv = cj[a]; float vv = cv[a];
            int b = a - 1;
            while (b >= s0 && cj[b] > jv) {
                cj[b + 1] = cj[b];
                cv[b + 1] = cv[b];
                b--;
            }
            cj[b + 1] = jv;
            cv[b + 1] = vv;
        }
    }
    __syncthreads();

    // bitmask fixed-point: mask_j <- !(exists i<j: mask_i & edge(i,j))
    for (int it = 0; it < 200; it++) {
        if (t < NW) ssup[t] = 0u;
        __syncthreads();
#pragma unroll
        for (int k = 0; k < 6; k++) {
            int i = base + k;
            if (i < N && (smask[i >> 5] & (1u << (i & 31)))) {
                int s0 = srow[i], s1 = srow[i + 1];
                for (int e = s0; e < s1; e++) {
                    int j = cj[e];
                    atomicOr(&ssup[j >> 5], 1u << (j & 31));
                }
            }
        }
        __syncthreads();
        int change = 0;
        if (t < NW) {
            unsigned nm = ~ssup[t];          // tail bits: never suppressed, stay 1
            if (nm != smask[t]) change = 1;
            smask[t] = nm;
        }
        if (!__syncthreads_or(change)) break;
    }
    __syncthreads();

    // merge + outputs (CSR already sorted; rows striped by t)
    for (int i = t; i < N; i += 1024) {
        float4 Ai = g_boxA[i];
        float4 Bi = g_boxB[i];
        float s = Bi.w;
        float a0 = s * Ai.x, a1 = s * Ai.y, a2 = s * Ai.z;
        float a3 = s * Ai.w, a4 = s * Bi.x, a5 = s * Bi.y;
        float w = s;
        unsigned m = (smask[i >> 5] >> (i & 31)) & 1u;
        if (m) {
            int s0 = srow[i], s1 = srow[i + 1];
            for (int e = s0; e < s1; e++) {
                float vv = cv[e];
                if (vv > NMS_TH) {           // strict > for merge weights
                    int jj = cj[e];
                    float4 Aj = g_boxA[jj];
                    float4 Bj = g_boxB[jj];
                    float wt = vv * Bj.w;
                    w += wt;
                    a0 += wt * Aj.x; a1 += wt * Aj.y; a2 += wt * Aj.z;
                    a3 += wt * Aj.w; a4 += wt * Bj.x; a5 += wt * Bj.y;
                }
            }
        }
        float inv = 1.0f / w;
        out[i * 6 + 0] = a0 * inv; out[i * 6 + 1] = a1 * inv;
        out[i * 6 + 2] = a2 * inv; out[i * 6 + 3] = a3 * inv;
        out[i * 6 + 4] = a4 * inv; out[i * 6 + 5] = a5 * inv;
        out[N * 6 + i] = m ? 1.0f : 0.0f;
        out[N * 7 + i] = s;
    }
}

// ---------------- launch ----------------
extern "C" void kernel_launch(void* const* d_in, const int* in_sizes, int n_in,
                              void* d_out, int out_size) {
    const float* boxes = (const float*)d_in[0];
    const float* scores = (const float*)d_in[1];
    float* out = (float*)d_out;

    const int post_smem = POST_SMEM_INTS * 4;   // ~114 KB dynamic shared
    cudaFuncSetAttribute(k_post, cudaFuncAttributeMaxDynamicSharedMemorySize, post_smem);

    k_rank<<<dim3(12, NCHUNK), 256>>>(scores);
    k_scatter<<<24, 256>>>(boxes, scores);
    k_edges<<<(N * 3 * 32 + 255) / 256, 256>>>();
    k_post<<<1, 1024, post_smem>>>(out);
}

// round 12
// speedup vs baseline: 1.2615x; 1.2615x over previous
#include <cuda_runtime.h>

#define N 6000
#define NMS_TH 0.7f
#define MAX_E (1 << 20)
#define NCHUNK 12      // rank chunks of 500
#define GC 12          // cells per axis (cell size 16 over [0,192))
#define NCELL (GC*GC*GC)
#define SE_CAP 8000    // shared-memory CSR capacity
#define NW 188         // ceil(6000/32) mask words
#define POST_SMEM_INTS ((N + 1) + N + SE_CAP + SE_CAP + NW + NW)

// ---------------- device scratch ----------------
__device__ int           g_rankpart[NCHUNK * N];
__device__ float4        g_filt[N];              // cx, cy, cz, R2 (rank order)
__device__ float4        g_boxA[N];              // x1, y1, x2, y2 (rank order)
__device__ float4        g_boxB[N];              // z1, z2, area, score (rank order)
__device__ int           g_cellid[N];
__device__ int           g_cellcnt[NCELL];
__device__ int           g_celloff[NCELL + 1];
__device__ float4        g_cfilt[N];             // filter data in cell-list order
__device__ int           g_crank[N];             // rank index in cell-list order
__device__ int           g_rowcnt[N];
__device__ int           g_rowoff[N + 1];
__device__ int           g_csrj[MAX_E];
__device__ float         g_csrv[MAX_E];
__device__ unsigned int  g_eij[MAX_E];           // (i<<16)|j, i<j
__device__ float         g_ev[MAX_E];
__device__ int           g_ecount;
__device__ int           g_done;                 // last-block detector for k_scatter
__device__ unsigned int  g_maskw[NW];

// ---------------- K1: partial rank counts, 2 rows per thread + zero counters ----------------
__global__ void k_rank(const float* __restrict__ scores) {
    __shared__ float ss[500];
    int tx = threadIdx.x;
    int j0 = blockIdx.y * 500;
    for (int jj = tx; jj < 500; jj += 256) ss[jj] = scores[j0 + jj];

    if (blockIdx.x == 0 && blockIdx.y == 0) {
        for (int c = tx; c < NCELL; c += 256) g_cellcnt[c] = 0;
        for (int c = tx; c < N; c += 256) g_rowcnt[c] = 0;
        if (tx == 0) { g_ecount = 0; g_done = 0; }
    }
    __syncthreads();

    int i0 = blockIdx.x * 512 + tx;
    int i1 = i0 + 256;
    float s0 = (i0 < N) ? scores[i0] : 0.0f;
    float s1 = (i1 < N) ? scores[i1] : 0.0f;
    int c0 = 0, c1 = 0;
#pragma unroll 5
    for (int jj = 0; jj < 500; jj++) {
        float t = ss[jj];
        int jg = j0 + jj;
        c0 += (t > s0) || (t == s0 && jg < i0);
        c1 += (t > s1) || (t == s1 && jg < i1);
    }
    if (i0 < N) g_rankpart[blockIdx.y * N + i0] = c0;
    if (i1 < N) g_rankpart[blockIdx.y * N + i1] = c1;
}

// ---------------- K2: scatter + cell binning; last block (512 thr) does scan + fill ----------------
__global__ void k_scatter(const float* __restrict__ boxes,
                          const float* __restrict__ scores) {
    int gid = blockIdx.x * 512 + threadIdx.x;
    if (gid < N) {
        int c = 0;
#pragma unroll
        for (int k = 0; k < NCHUNK; k++) c += g_rankpart[k * N + gid];

        float x1 = boxes[gid * 6 + 0], y1 = boxes[gid * 6 + 1];
        float x2 = boxes[gid * 6 + 2], y2 = boxes[gid * 6 + 3];
        float z1 = boxes[gid * 6 + 4], z2 = boxes[gid * 6 + 5];
        float s = scores[gid];
        g_boxA[c] = make_float4(x1, y1, x2, y2);
        g_boxB[c] = make_float4(z1, z2, (x2 - x1) * (y2 - y1) * (z2 - z1), s);
        float cx = (x2 + x1) * 0.5f, cy = (y2 + y1) * 0.5f, cz = (z1 + z2) * 0.5f;
        float rx = (x2 - x1) * 0.5f, ry = (y2 - y1) * 0.5f, rz = (z2 - z1) * 0.5f;
        float R2 = 0.36f * (rx * rx + ry * ry + rz * rz);
        R2 = R2 * 1.002f + 1e-3f;   // margin vs fp rounding (necessary-condition filter)
        g_filt[c] = make_float4(cx, cy, cz, R2);

        int ix = min(GC - 1, max(0, __float2int_rd(cx * 0.0625f)));
        int iy = min(GC - 1, max(0, __float2int_rd(cy * 0.0625f)));
        int iz = min(GC - 1, max(0, __float2int_rd(cz * 0.0625f)));
        int cid = (iz * GC + iy) * GC + ix;
        g_cellid[c] = cid;
        atomicAdd(&g_cellcnt[cid], 1);
    }

    // ---- last-block-done: scan + cell-ordered fill ----
    __threadfence();
    __shared__ int isLast;
    if (threadIdx.x == 0)
        isLast = (atomicAdd(&g_done, 1) == (int)gridDim.x - 1);
    __syncthreads();
    if (!isLast) return;
    __threadfence();   // acquire: make all blocks' writes visible

    __shared__ int wsum[16];
    __shared__ int sfill[NCELL];
    int t = threadIdx.x;          // 512 threads
    // each thread scans 4 cells (4*512 = 2048 >= 1728)
    int cnt4[4];
    int local = 0;
#pragma unroll
    for (int k = 0; k < 4; k++) {
        int idx = t * 4 + k;
        cnt4[k] = (idx < NCELL) ? g_cellcnt[idx] : 0;
        local += cnt4[k];
    }
    int v = local;
#pragma unroll
    for (int o = 1; o < 32; o <<= 1) {
        int u = __shfl_up_sync(0xFFFFFFFFu, v, o);
        if ((t & 31) >= o) v += u;
    }
    if ((t & 31) == 31) wsum[t >> 5] = v;
    __syncthreads();
    if (t < 16) {
        int w = wsum[t];
#pragma unroll
        for (int o = 1; o < 16; o <<= 1) {
            int u = __shfl_up_sync(0xFFFFu, w, o);
            if (t >= o) w += u;
        }
        wsum[t] = w;
    }
    __syncthreads();
    int run = v - local + ((t >= 32) ? wsum[(t >> 5) - 1] : 0);
#pragma unroll
    for (int k = 0; k < 4; k++) {
        int idx = t * 4 + k;
        if (idx < NCELL) {
            sfill[idx] = run;
            g_celloff[idx] = run;
            run += cnt4[k];
        }
    }
    if (t == 511) g_celloff[NCELL] = run;
    __syncthreads();
    for (int c = t; c < N; c += 512) {
        int cid = g_cellid[c];
        int pos = atomicAdd(&sfill[cid], 1);
        g_crank[pos] = c;
        g_cfilt[pos] = g_filt[c];
    }
}

// ---------------- K3: edge extraction, one warp per (j, z-row) ----------------
// Coverage proof: DIoU>=0.7 => per-dim |dc| <= 0.6*min(halfwidth) <= 13.2 < 16,
// so the 27-cell neighborhood of j's cell contains every qualifying partner.
__global__ void k_edges() {
    int gt = blockIdx.x * 256 + threadIdx.x;
    int task = gt >> 5;
    int lane = gt & 31;
    if (task >= N * 3) return;
    int j = task / 3;
    int dz = task - j * 3 - 1;     // -1, 0, +1

    float4 bf = g_filt[j];
    int czi = min(GC - 1, max(0, __float2int_rd(bf.z * 0.0625f)));
    int zz = czi + dz;
    if (zz < 0 || zz >= GC) return;

    float4 A = g_boxA[j];          // x1,y1,x2,y2
    float4 B = g_boxB[j];          // z1,z2,area,score

    int cxi = min(GC - 1, max(0, __float2int_rd(bf.x * 0.0625f)));
    int cyi = min(GC - 1, max(0, __float2int_rd(bf.y * 0.0625f)));
    int ylo = max(0, cyi - 1), yhi = min(GC - 1, cyi + 1);
    int xlo = max(0, cxi - 1), xhi = min(GC - 1, cxi + 1);

    for (int yy = ylo; yy <= yhi; yy++) {
        int rowbase = (zz * GC + yy) * GC;
        int s = g_celloff[rowbase + xlo];
        int e = g_celloff[rowbase + xhi + 1];   // x-contiguous cells: one span
        for (int p = s + lane; p < e; p += 32) {
            float4 f = g_cfilt[p];              // contiguous per-warp load
            int i = g_crank[p];
            float dx = bf.x - f.x, dy = bf.y - f.y, dz2 = bf.z - f.z;
            float d2 = dx * dx + dy * dy + dz2 * dz2;
            if (i < j && d2 <= fminf(f.w, bf.w)) {
                float4 Ai = g_boxA[i];
                float4 Bi = g_boxB[i];
                float iw = fminf(Ai.z, A.z) - fmaxf(Ai.x, A.x);
                float ih = fminf(Ai.w, A.w) - fmaxf(Ai.y, A.y);
                float dp = fminf(Bi.y, B.y) - fmaxf(Bi.x, B.x);
                if (iw > 0.0f && ih > 0.0f && dp > 0.0f) {
                    float inter = iw * ih * dp;
                    float uni = Bi.z + B.z - inter + 1e-7f;
                    float ow = fmaxf(Ai.z, A.z) - fminf(Ai.x, A.x);
                    float oh = fmaxf(Ai.w, A.w) - fminf(Ai.y, A.y);
                    float od = fmaxf(Bi.y, B.y) - fminf(Bi.x, B.x);
                    float odiag = ow * ow + oh * oh + od * od + 1e-7f;
                    float v = inter / uni - d2 / odiag;
                    if (v >= NMS_TH) {
                        int e2 = atomicAdd(&g_ecount, 1);
                        if (e2 < MAX_E) {
                            g_eij[e2] = ((unsigned)i << 16) | (unsigned)j;
                            g_ev[e2] = v;
                            atomicAdd(&g_rowcnt[i], 1);
                        }
                    }
                }
            }
        }
    }
}

// ---------------- K4: all-shared CSR build + sort + bitmask fixed-point (1 block) ----------------
__global__ void k_post() {
    extern __shared__ int dyn[];
    int*          srow  = dyn;                      // N+1 row offsets
    int*          sfil  = srow + (N + 1);           // N fill cursors
    int*          scj   = sfil + N;                 // SE_CAP csr j
    float*        scv   = (float*)(scj + SE_CAP);   // SE_CAP csr v
    unsigned int* smask = (unsigned int*)(scv + SE_CAP);
    unsigned int* ssup  = smask + NW;
    __shared__ int wsum[32];
    int t = threadIdx.x;

    // offsets: per-thread chunk of 6 rows, shuffle-based block scan
    int base = t * 6;
    int cnt6[6];
    int local = 0;
#pragma unroll
    for (int k = 0; k < 6; k++) {
        int idx = base + k;
        cnt6[k] = (idx < N) ? g_rowcnt[idx] : 0;
        local += cnt6[k];
    }
    int v = local;
#pragma unroll
    for (int o = 1; o < 32; o <<= 1) {
        int u = __shfl_up_sync(0xFFFFFFFFu, v, o);
        if ((t & 31) >= o) v += u;
    }
    if ((t & 31) == 31) wsum[t >> 5] = v;
    __syncthreads();
    if (t < 32) {
        int w = wsum[t];
#pragma unroll
        for (int o = 1; o < 32; o <<= 1) {
            int u = __shfl_up_sync(0xFFFFFFFFu, w, o);
            if (t >= o) w += u;
        }
        wsum[t] = w;
    }
    __syncthreads();
    int run = v - local + ((t >= 32) ? wsum[(t >> 5) - 1] : 0);
#pragma unroll
    for (int k = 0; k < 6; k++) {
        int idx = base + k;
        if (idx < N) {
            srow[idx] = run;
            sfil[idx] = run;
            g_rowoff[idx] = run;
            run += cnt6[k];
        }
    }
    if (t == 1023) { srow[N] = run; g_rowoff[N] = run; }
    if (t < NW) smask[t] = 0xFFFFFFFFu;
    __syncthreads();

    int E = g_ecount;
    if (E > MAX_E) E = MAX_E;

    if (E <= SE_CAP) {
        // ---- shared-memory CSR path ----
        for (int e = t; e < E; e += 1024) {
            unsigned p = g_eij[e];
            int i = p >> 16;
            int pos = atomicAdd(&sfil[i], 1);
            scj[pos] = (int)(p & 0xFFFF);
            scv[pos] = g_ev[e];
        }
        __syncthreads();

        // per-row insertion sort by j in shared (determinism)
        for (int i = t; i < N; i += 1024) {
            int s0 = srow[i], s1 = srow[i + 1];
            for (int a = s0 + 1; a < s1; a++) {
                int jv = scj[a]; float vv = scv[a];
                int b = a - 1;
                while (b >= s0 && scj[b] > jv) {
                    scj[b + 1] = scj[b];
                    scv[b + 1] = scv[b];
                    b--;
                }
                scj[b + 1] = jv;
                scv[b + 1] = vv;
            }
        }
        __syncthreads();

        // bitmask fixed-point over shared CSR rows
        for (int it = 0; it < 200; it++) {
            if (t < NW) ssup[t] = 0u;
            __syncthreads();
#pragma unroll
            for (int k = 0; k < 6; k++) {
                int i = base + k;
                if (i < N && (smask[i >> 5] & (1u << (i & 31)))) {
                    int s0 = srow[i], s1 = srow[i + 1];
                    for (int e = s0; e < s1; e++) {
                        int j = scj[e];
                        atomicOr(&ssup[j >> 5], 1u << (j & 31));
                    }
                }
            }
            __syncthreads();
            int change = 0;
            if (t < NW) {
                unsigned nm = ~ssup[t];      // tail bits: never suppressed, stay 1
                if (nm != smask[t]) change = 1;
                smask[t] = nm;
            }
            if (!__syncthreads_or(change)) break;
        }
        // copy sorted CSR out for k_final
        for (int e = t; e < E; e += 1024) {
            g_csrj[e] = scj[e];
            g_csrv[e] = scv[e];
        }
    } else {
        // ---- global fallback path ----
        for (int e = t; e < E; e += 1024) {
            unsigned p = g_eij[e];
            int i = p >> 16;
            int pos = atomicAdd(&sfil[i], 1);
            g_csrj[pos] = (int)(p & 0xFFFF);
            g_csrv[pos] = g_ev[e];
        }
        __syncthreads();
        for (int i = t; i < N; i += 1024) {
            int s0 = srow[i], s1 = srow[i + 1];
            for (int a = s0 + 1; a < s1; a++) {
                int jv = g_csrj[a]; float vv = g_csrv[a];
                int b = a - 1;
                while (b >= s0 && g_csrj[b] > jv) {
                    g_csrj[b + 1] = g_csrj[b];
                    g_csrv[b + 1] = g_csrv[b];
                    b--;
                }
                g_csrj[b + 1] = jv;
                g_csrv[b + 1] = vv;
            }
        }
        __syncthreads();
        for (int it = 0; it < 200; it++) {
            if (t < NW) ssup[t] = 0u;
            __syncthreads();
            for (int e = t; e < E; e += 1024) {
                unsigned p = g_eij[e];
                int i = p >> 16, j = p & 0xFFFF;
                if (smask[i >> 5] & (1u << (i & 31)))
                    atomicOr(&ssup[j >> 5], 1u << (j & 31));
            }
            __syncthreads();
            int change = 0;
            if (t < NW) {
                unsigned nm = ~ssup[t];
                if (nm != smask[t]) change = 1;
                smask[t] = nm;
            }
            if (!__syncthreads_or(change)) break;
        }
    }
    if (t < NW) g_maskw[t] = smask[t];
}

// ---------------- K5: merge from CSR + write outputs (multi-block) ----------------
__global__ void k_final(float* __restrict__ out) {
    int i = blockIdx.x * 256 + threadIdx.x;
    if (i >= N) return;
    float4 Ai = g_boxA[i];
    float4 Bi = g_boxB[i];
    float s = Bi.w;
    float a0 = s * Ai.x, a1 = s * Ai.y, a2 = s * Ai.z;
    float a3 = s * Ai.w, a4 = s * Bi.x, a5 = s * Bi.y;
    float w = s;
    unsigned m = (g_maskw[i >> 5] >> (i & 31)) & 1u;
    if (m) {
        int s0 = g_rowoff[i], s1 = g_rowoff[i + 1];
        for (int e = s0; e < s1; e++) {
            float v = g_csrv[e];
            if (v > NMS_TH) {           // strict > for merge weights
                int j = g_csrj[e];
                float4 Aj = g_boxA[j];
                float4 Bj = g_boxB[j];
                float wt = v * Bj.w;
                w += wt;
                a0 += wt * Aj.x; a1 += wt * Aj.y; a2 += wt * Aj.z;
                a3 += wt * Aj.w; a4 += wt * Bj.x; a5 += wt * Bj.y;
            }
        }
    }
    float inv = 1.0f / w;
    out[i * 6 + 0] = a0 * inv; out[i * 6 + 1] = a1 * inv;
    out[i * 6 + 2] = a2 * inv; out[i * 6 + 3] = a3 * inv;
    out[i * 6 + 4] = a4 * inv; out[i * 6 + 5] = a5 * inv;
    out[N * 6 + i] = m ? 1.0f : 0.0f;
    out[N * 7 + i] = s;
}

// ---------------- launch ----------------
extern "C" void kernel_launch(void* const* d_in, const int* in_sizes, int n_in,
                              void* d_out, int out_size) {
    const float* boxes = (const float*)d_in[0];
    const float* scores = (const float*)d_in[1];
    float* out = (float*)d_out;

    const int post_smem = POST_SMEM_INTS * 4;   // ~114 KB dynamic shared
    cudaFuncSetAttribute(k_post, cudaFuncAttributeMaxDynamicSharedMemorySize, post_smem);

    k_rank<<<dim3(12, NCHUNK), 256>>>(scores);
    k_scatter<<<12, 512>>>(boxes, scores);
    k_edges<<<(N * 3 * 32 + 255) / 256, 256>>>();
    k_post<<<1, 1024, post_smem>>>();
    k_final<<<24, 256>>>(out);
}

// round 13
// speedup vs baseline: 1.3617x; 1.0794x over previous
#include <cuda_runtime.h>

#define N 6000
#define NMS_TH 0.7f
#define MAX_E (1 << 20)
#define NCHUNK 12      // rank chunks of 500
#define GC 12          // cells per axis (cell size 16 over [0,192))
#define NCELL (GC*GC*GC)
#define SE_CAP 8000    // shared-memory CSR capacity
#define NW 188         // ceil(6000/32) mask words
#define POST_SMEM_INTS ((N + 1) + N + SE_CAP + SE_CAP + NW + NW)

// ---------------- device scratch ----------------
__device__ int           g_rankpart[NCHUNK * N];
__device__ float4        g_filt[N];              // cx, cy, cz, R2 (rank order)
__device__ float4        g_boxA[N];              // x1, y1, x2, y2 (rank order)
__device__ float4        g_boxB[N];              // z1, z2, area, score (rank order)
__device__ int           g_cellid[N];
__device__ int           g_cellcnt[NCELL];
__device__ int           g_celloff[NCELL + 1];
__device__ float4        g_cfilt[N];             // filter data in cell-list order
__device__ int           g_crank[N];             // rank index in cell-list order
__device__ int           g_rowcnt[N];
__device__ int           g_rowoff[N + 1];
__device__ int           g_fill[N];
__device__ unsigned int  g_eij[MAX_E];           // (i<<16)|j, i<j
__device__ float         g_ev[MAX_E];
__device__ int           g_csrj[MAX_E];
__device__ float         g_csrv[MAX_E];
__device__ int           g_ecount;
__device__ unsigned int  g_maskw[NW];

// ---------------- K1: partial rank counts, 2 rows per thread + zero counters ----------------
__global__ void k_rank(const float* __restrict__ scores) {
    __shared__ float ss[500];
    int tx = threadIdx.x;
    int j0 = blockIdx.y * 500;
    for (int jj = tx; jj < 500; jj += 256) ss[jj] = scores[j0 + jj];

    if (blockIdx.x == 0 && blockIdx.y == 0) {
        for (int c = tx; c < NCELL; c += 256) g_cellcnt[c] = 0;
        for (int c = tx; c < N; c += 256) g_rowcnt[c] = 0;
        if (tx == 0) g_ecount = 0;
    }
    __syncthreads();

    int i0 = blockIdx.x * 512 + tx;
    int i1 = i0 + 256;
    float s0 = (i0 < N) ? scores[i0] : 0.0f;
    float s1 = (i1 < N) ? scores[i1] : 0.0f;
    int c0 = 0, c1 = 0;
#pragma unroll 5
    for (int jj = 0; jj < 500; jj++) {
        float t = ss[jj];
        int jg = j0 + jj;
        c0 += (t > s0) || (t == s0 && jg < i0);
        c1 += (t > s1) || (t == s1 && jg < i1);
    }
    if (i0 < N) g_rankpart[blockIdx.y * N + i0] = c0;
    if (i1 < N) g_rankpart[blockIdx.y * N + i1] = c1;
}

// ---------------- K2: scatter into sorted order + cell binning (multi-block) ----------------
__global__ void k_scatter(const float* __restrict__ boxes,
                          const float* __restrict__ scores) {
    int gid = blockIdx.x * 256 + threadIdx.x;
    if (gid >= N) return;

    int c = 0;
#pragma unroll
    for (int k = 0; k < NCHUNK; k++) c += g_rankpart[k * N + gid];

    float x1 = boxes[gid * 6 + 0], y1 = boxes[gid * 6 + 1];
    float x2 = boxes[gid * 6 + 2], y2 = boxes[gid * 6 + 3];
    float z1 = boxes[gid * 6 + 4], z2 = boxes[gid * 6 + 5];
    float s = scores[gid];
    g_boxA[c] = make_float4(x1, y1, x2, y2);
    g_boxB[c] = make_float4(z1, z2, (x2 - x1) * (y2 - y1) * (z2 - z1), s);
    float cx = (x2 + x1) * 0.5f, cy = (y2 + y1) * 0.5f, cz = (z1 + z2) * 0.5f;
    float rx = (x2 - x1) * 0.5f, ry = (y2 - y1) * 0.5f, rz = (z2 - z1) * 0.5f;
    float R2 = 0.36f * (rx * rx + ry * ry + rz * rz);
    R2 = R2 * 1.002f + 1e-3f;   // margin vs fp rounding (necessary-condition filter)
    g_filt[c] = make_float4(cx, cy, cz, R2);

    int ix = min(GC - 1, max(0, __float2int_rd(cx * 0.0625f)));
    int iy = min(GC - 1, max(0, __float2int_rd(cy * 0.0625f)));
    int iz = min(GC - 1, max(0, __float2int_rd(cz * 0.0625f)));
    int cid = (iz * GC + iy) * GC + ix;
    g_cellid[c] = cid;
    atomicAdd(&g_cellcnt[cid], 1);
}

// ---------------- K3: cell scan (shuffle-based) + fill cell-ordered arrays ----------------
__global__ void k_cell() {
    __shared__ int wsum[32];
    __shared__ int sfill[NCELL];
    int t = threadIdx.x;
    int a = (2 * t < NCELL) ? g_cellcnt[2 * t] : 0;
    int b = (2 * t + 1 < NCELL) ? g_cellcnt[2 * t + 1] : 0;
    int local = a + b;

    int v = local;
#pragma unroll
    for (int o = 1; o < 32; o <<= 1) {
        int u = __shfl_up_sync(0xFFFFFFFFu, v, o);
        if ((t & 31) >= o) v += u;
    }
    if ((t & 31) == 31) wsum[t >> 5] = v;
    __syncthreads();
    if (t < 32) {
        int w = wsum[t];
#pragma unroll
        for (int o = 1; o < 32; o <<= 1) {
            int u = __shfl_up_sync(0xFFFFFFFFu, w, o);
            if (t >= o) w += u;
        }
        wsum[t] = w;
    }
    __syncthreads();
    int incl = v + ((t >= 32) ? wsum[(t >> 5) - 1] : 0);
    int run = incl - local;
    if (2 * t < NCELL)     { sfill[2 * t] = run;         g_celloff[2 * t] = run; }
    if (2 * t + 1 < NCELL) { sfill[2 * t + 1] = run + a; g_celloff[2 * t + 1] = run + a; }
    if (t == 1023) g_celloff[NCELL] = incl;
    __syncthreads();
    for (int c = t; c < N; c += 1024) {
        int cid = g_cellid[c];
        int pos = atomicAdd(&sfill[cid], 1);
        g_crank[pos] = c;
        g_cfilt[pos] = g_filt[c];
    }
}

// ---------------- K4: edge extraction, one warp per (cell-list slot, z-row) ----------------
// Coverage proof: DIoU>=0.7 => per-dim |dc| <= 0.6*min(halfwidth) <= 13.2 < 16,
// so the 27-cell neighborhood of j's cell contains every qualifying partner.
// Tasks walk the CELL LIST (p), not rank order: adjacent warps handle spatially
// adjacent j and re-read the same candidate spans -> L1-resident span data.
__global__ void k_edges() {
    int gt = blockIdx.x * 256 + threadIdx.x;
    int task = gt >> 5;
    int lane = gt & 31;
    if (task >= N * 3) return;
    int p0 = task / 3;
    int dz = task - p0 * 3 - 1;    // -1, 0, +1
    int j = g_crank[p0];

    float4 bf = g_cfilt[p0];       // contiguous across warps
    int czi = min(GC - 1, max(0, __float2int_rd(bf.z * 0.0625f)));
    int zz = czi + dz;
    if (zz < 0 || zz >= GC) return;

    float4 A = g_boxA[j];          // x1,y1,x2,y2
    float4 B = g_boxB[j];          // z1,z2,area,score

    int cxi = min(GC - 1, max(0, __float2int_rd(bf.x * 0.0625f)));
    int cyi = min(GC - 1, max(0, __float2int_rd(bf.y * 0.0625f)));
    int ylo = max(0, cyi - 1), yhi = min(GC - 1, cyi + 1);
    int xlo = max(0, cxi - 1), xhi = min(GC - 1, cxi + 1);

    for (int yy = ylo; yy <= yhi; yy++) {
        int rowbase = (zz * GC + yy) * GC;
        int s = g_celloff[rowbase + xlo];
        int e = g_celloff[rowbase + xhi + 1];   // x-contiguous cells: one span
        for (int p = s + lane; p < e; p += 32) {
            float4 f = g_cfilt[p];              // L1-shared across neighbor warps
            int i = g_crank[p];
            float dx = bf.x - f.x, dy = bf.y - f.y, dz2 = bf.z - f.z;
            float d2 = dx * dx + dy * dy + dz2 * dz2;
            if (i < j && d2 <= fminf(f.w, bf.w)) {
                float4 Ai = g_boxA[i];
                float4 Bi = g_boxB[i];
                float iw = fminf(Ai.z, A.z) - fmaxf(Ai.x, A.x);
                float ih = fminf(Ai.w, A.w) - fmaxf(Ai.y, A.y);
                float dp = fminf(Bi.y, B.y) - fmaxf(Bi.x, B.x);
                if (iw > 0.0f && ih > 0.0f && dp > 0.0f) {
                    float inter = iw * ih * dp;
                    float uni = Bi.z + B.z - inter + 1e-7f;
                    float ow = fmaxf(Ai.z, A.z) - fminf(Ai.x, A.x);
                    float oh = fmaxf(Ai.w, A.w) - fminf(Ai.y, A.y);
                    float od = fmaxf(Bi.y, B.y) - fminf(Bi.x, B.x);
                    float odiag = ow * ow + oh * oh + od * od + 1e-7f;
                    float v = inter / uni - d2 / odiag;
                    if (v >= NMS_TH) {
                        int e2 = atomicAdd(&g_ecount, 1);
                        if (e2 < MAX_E) {
                            g_eij[e2] = ((unsigned)i << 16) | (unsigned)j;
                            g_ev[e2] = v;
                            atomicAdd(&g_rowcnt[i], 1);
                        }
                    }
                }
            }
        }
    }
}

// ---------------- K5: all-shared CSR build + sort + bitmask fixed-point (1 block) ----------------
__global__ void k_post() {
    extern __shared__ int dyn[];
    int*          srow  = dyn;                      // N+1 row offsets
    int*          sfil  = srow + (N + 1);           // N fill cursors
    int*          scj   = sfil + N;                 // SE_CAP csr j
    float*        scv   = (float*)(scj + SE_CAP);   // SE_CAP csr v
    unsigned int* smask = (unsigned int*)(scv + SE_CAP);
    unsigned int* ssup  = smask + NW;
    __shared__ int wsum[32];
    int t = threadIdx.x;

    // offsets: per-thread chunk of 6 rows, shuffle-based block scan
    int base = t * 6;
    int cnt6[6];
    int local = 0;
#pragma unroll
    for (int k = 0; k < 6; k++) {
        int idx = base + k;
        cnt6[k] = (idx < N) ? g_rowcnt[idx] : 0;
        local += cnt6[k];
    }
    int v = local;
#pragma unroll
    for (int o = 1; o < 32; o <<= 1) {
        int u = __shfl_up_sync(0xFFFFFFFFu, v, o);
        if ((t & 31) >= o) v += u;
    }
    if ((t & 31) == 31) wsum[t >> 5] = v;
    __syncthreads();
    if (t < 32) {
        int w = wsum[t];
#pragma unroll
        for (int o = 1; o < 32; o <<= 1) {
            int u = __shfl_up_sync(0xFFFFFFFFu, w, o);
            if (t >= o) w += u;
        }
        wsum[t] = w;
    }
    __syncthreads();
    int run = v - local + ((t >= 32) ? wsum[(t >> 5) - 1] : 0);
#pragma unroll
    for (int k = 0; k < 6; k++) {
        int idx = base + k;
        if (idx < N) {
            srow[idx] = run;
            sfil[idx] = run;
            g_rowoff[idx] = run;
            run += cnt6[k];
        }
    }
    if (t == 1023) { srow[N] = run; g_rowoff[N] = run; }
    if (t < NW) smask[t] = 0xFFFFFFFFu;
    __syncthreads();

    int E = g_ecount;
    if (E > MAX_E) E = MAX_E;

    if (E <= SE_CAP) {
        // ---- shared-memory CSR path ----
        for (int e = t; e < E; e += 1024) {
            unsigned p = g_eij[e];
            int i = p >> 16;
            int pos = atomicAdd(&sfil[i], 1);
            scj[pos] = (int)(p & 0xFFFF);
            scv[pos] = g_ev[e];
        }
        __syncthreads();

        // per-row insertion sort by j in shared (determinism)
        for (int i = t; i < N; i += 1024) {
            int s0 = srow[i], s1 = srow[i + 1];
            for (int a = s0 + 1; a < s1; a++) {
                int jv = scj[a]; float vv = scv[a];
                int b = a - 1;
                while (b >= s0 && scj[b] > jv) {
                    scj[b + 1] = scj[b];
                    scv[b + 1] = scv[b];
                    b--;
                }
                scj[b + 1] = jv;
                scv[b + 1] = vv;
            }
        }
        __syncthreads();

        // bitmask fixed-point over shared CSR rows
        for (int it = 0; it < 200; it++) {
            if (t < NW) ssup[t] = 0u;
            __syncthreads();
#pragma unroll
            for (int k = 0; k < 6; k++) {
                int i = base + k;
                if (i < N && (smask[i >> 5] & (1u << (i & 31)))) {
                    int s0 = srow[i], s1 = srow[i + 1];
                    for (int e = s0; e < s1; e++) {
                        int j = scj[e];
                        atomicOr(&ssup[j >> 5], 1u << (j & 31));
                    }
                }
            }
            __syncthreads();
            int change = 0;
            if (t < NW) {
                unsigned nm = ~ssup[t];      // tail bits: never suppressed, stay 1
                if (nm != smask[t]) change = 1;
                smask[t] = nm;
            }
            if (!__syncthreads_or(change)) break;
        }
        // copy sorted CSR out for k_final
        for (int e = t; e < E; e += 1024) {
            g_csrj[e] = scj[e];
            g_csrv[e] = scv[e];
        }
    } else {
        // ---- global fallback path ----
        for (int i = t; i < N; i += 1024) g_fill[i] = srow[i];
        __syncthreads();
        for (int e = t; e < E; e += 1024) {
            unsigned p = g_eij[e];
            int i = p >> 16;
            int pos = atomicAdd(&g_fill[i], 1);
            g_csrj[pos] = (int)(p & 0xFFFF);
            g_csrv[pos] = g_ev[e];
        }
        __syncthreads();
        for (int i = t; i < N; i += 1024) {
            int s0 = srow[i], s1 = srow[i + 1];
            for (int a = s0 + 1; a < s1; a++) {
                int jv = g_csrj[a]; float vv = g_csrv[a];
                int b = a - 1;
                while (b >= s0 && g_csrj[b] > jv) {
                    g_csrj[b + 1] = g_csrj[b];
                    g_csrv[b + 1] = g_csrv[b];
                    b--;
                }
                g_csrj[b + 1] = jv;
                g_csrv[b + 1] = vv;
            }
        }
        __syncthreads();
        for (int it = 0; it < 200; it++) {
            if (t < NW) ssup[t] = 0u;
            __syncthreads();
            for (int e = t; e < E; e += 1024) {
                unsigned p = g_eij[e];
                int i = p >> 16, j = p & 0xFFFF;
                if (smask[i >> 5] & (1u << (i & 31)))
                    atomicOr(&ssup[j >> 5], 1u << (j & 31));
            }
            __syncthreads();
            int change = 0;
            if (t < NW) {
                unsigned nm = ~ssup[t];
                if (nm != smask[t]) change = 1;
                smask[t] = nm;
            }
            if (!__syncthreads_or(change)) break;
        }
    }
    if (t < NW) g_maskw[t] = smask[t];
}

// ---------------- K6: merge from CSR + write outputs (multi-block) ----------------
__global__ void k_final(float* __restrict__ out) {
    int i = blockIdx.x * 256 + threadIdx.x;
    if (i >= N) return;
    float4 Ai = g_boxA[i];
    float4 Bi = g_boxB[i];
    float s = Bi.w;
    float a0 = s * Ai.x, a1 = s * Ai.y, a2 = s * Ai.z;
    float a3 = s * Ai.w, a4 = s * Bi.x, a5 = s * Bi.y;
    float w = s;
    unsigned m = (g_maskw[i >> 5] >> (i & 31)) & 1u;
    if (m) {
        int s0 = g_rowoff[i], s1 = g_rowoff[i + 1];
        for (int e = s0; e < s1; e++) {
            float v = g_csrv[e];
            if (v > NMS_TH) {           // strict > for merge weights
                int j = g_csrj[e];
                float4 Aj = g_boxA[j];
                float4 Bj = g_boxB[j];
                float wt = v * Bj.w;
                w += wt;
                a0 += wt * Aj.x; a1 += wt * Aj.y; a2 += wt * Aj.z;
                a3 += wt * Aj.w; a4 += wt * Bj.x; a5 += wt * Bj.y;
            }
        }
    }
    float inv = 1.0f / w;
    out[i * 6 + 0] = a0 * inv; out[i * 6 + 1] = a1 * inv;
    out[i * 6 + 2] = a2 * inv; out[i * 6 + 3] = a3 * inv;
    out[i * 6 + 4] = a4 * inv; out[i * 6 + 5] = a5 * inv;
    out[N * 6 + i] = m ? 1.0f : 0.0f;
    out[N * 7 + i] = s;
}

// ---------------- launch ----------------
extern "C" void kernel_launch(void* const* d_in, const int* in_sizes, int n_in,
                              void* d_out, int out_size) {
    const float* boxes = (const float*)d_in[0];
    const float* scores = (const float*)d_in[1];
    float* out = (float*)d_out;

    const int post_smem = POST_SMEM_INTS * 4;   // ~114 KB dynamic shared
    cudaFuncSetAttribute(k_post, cudaFuncAttributeMaxDynamicSharedMemorySize, post_smem);

    k_rank<<<dim3(12, NCHUNK), 256>>>(scores);
    k_scatter<<<24, 256>>>(boxes, scores);
    k_cell<<<1, 1024>>>();
    k_edges<<<(N * 3 * 32 + 255) / 256, 256>>>();
    k_post<<<1, 1024, post_smem>>>();
    k_final<<<24, 256>>>(out);
}

// round 14
// speedup vs baseline: 1.4275x; 1.0483x over previous
#include <cuda_runtime.h>

#define N 6000
#define NMS_TH 0.7f
#define MAX_E (1 << 20)
#define NCHUNK 24      // rank chunks of 250
#define GC 12          // cells per axis (cell size 16 over [0,192))
#define NCELL (GC*GC*GC)
#define SE_CAP 8000    // shared-memory CSR capacity
#define NW 188         // ceil(6000/32) mask words
#define POST_SMEM_INTS ((N + 1) + N + SE_CAP + SE_CAP + NW + NW)
#define CCAP 128       // candidate chunk per block in k_edges
#define JCAP 32        // own-cell j chunk

// ---------------- device scratch ----------------
__device__ int           g_rankpart[NCHUNK * N];
__device__ float4        g_filt[N];              // cx, cy, cz, R2 (rank order)
__device__ float4        g_boxA[N];              // x1, y1, x2, y2 (rank order)
__device__ float4        g_boxB[N];              // z1, z2, area, score (rank order)
__device__ int           g_cellid[N];
__device__ int           g_cellcnt[NCELL];
__device__ int           g_celloff[NCELL + 1];
__device__ float4        g_cfilt[N];             // filter data in cell-list order
__device__ int           g_crank[N];             // rank index in cell-list order
__device__ int           g_rowcnt[N];
__device__ int           g_rowoff[N + 1];
__device__ int           g_fill[N];
__device__ unsigned int  g_eij[MAX_E];           // (i<<16)|j, i<j
__device__ float         g_ev[MAX_E];
__device__ int           g_csrj[MAX_E];
__device__ float         g_csrv[MAX_E];
__device__ int           g_ecount;
__device__ unsigned int  g_maskw[NW];

// ---------------- K1: partial rank counts, 2 rows per thread + zero counters ----------------
__global__ void k_rank(const float* __restrict__ scores) {
    __shared__ float ss[250];
    int tx = threadIdx.x;
    int j0 = blockIdx.y * 250;
    if (tx < 250) ss[tx] = scores[j0 + tx];

    if (blockIdx.x == 0 && blockIdx.y == 0) {
        for (int c = tx; c < NCELL; c += 256) g_cellcnt[c] = 0;
        for (int c = tx; c < N; c += 256) g_rowcnt[c] = 0;
        if (tx == 0) g_ecount = 0;
    }
    __syncthreads();

    int i0 = blockIdx.x * 512 + tx;
    int i1 = i0 + 256;
    float s0 = (i0 < N) ? scores[i0] : 0.0f;
    float s1 = (i1 < N) ? scores[i1] : 0.0f;
    int c0 = 0, c1 = 0;
#pragma unroll 5
    for (int jj = 0; jj < 250; jj++) {
        float t = ss[jj];
        int jg = j0 + jj;
        c0 += (t > s0) || (t == s0 && jg < i0);
        c1 += (t > s1) || (t == s1 && jg < i1);
    }
    if (i0 < N) g_rankpart[blockIdx.y * N + i0] = c0;
    if (i1 < N) g_rankpart[blockIdx.y * N + i1] = c1;
}

// ---------------- K2: scatter into sorted order + cell binning (multi-block) ----------------
__global__ void k_scatter(const float* __restrict__ boxes,
                          const float* __restrict__ scores) {
    int gid = blockIdx.x * 256 + threadIdx.x;
    if (gid >= N) return;

    int c = 0;
#pragma unroll
    for (int k = 0; k < NCHUNK; k++) c += g_rankpart[k * N + gid];

    float x1 = boxes[gid * 6 + 0], y1 = boxes[gid * 6 + 1];
    float x2 = boxes[gid * 6 + 2], y2 = boxes[gid * 6 + 3];
    float z1 = boxes[gid * 6 + 4], z2 = boxes[gid * 6 + 5];
    float s = scores[gid];
    g_boxA[c] = make_float4(x1, y1, x2, y2);
    g_boxB[c] = make_float4(z1, z2, (x2 - x1) * (y2 - y1) * (z2 - z1), s);
    float cx = (x2 + x1) * 0.5f, cy = (y2 + y1) * 0.5f, cz = (z1 + z2) * 0.5f;
    float rx = (x2 - x1) * 0.5f, ry = (y2 - y1) * 0.5f, rz = (z2 - z1) * 0.5f;
    float R2 = 0.36f * (rx * rx + ry * ry + rz * rz);
    R2 = R2 * 1.002f + 1e-3f;   // margin vs fp rounding (necessary-condition filter)
    g_filt[c] = make_float4(cx, cy, cz, R2);

    int ix = min(GC - 1, max(0, __float2int_rd(cx * 0.0625f)));
    int iy = min(GC - 1, max(0, __float2int_rd(cy * 0.0625f)));
    int iz = min(GC - 1, max(0, __float2int_rd(cz * 0.0625f)));
    int cid = (iz * GC + iy) * GC + ix;
    g_cellid[c] = cid;
    atomicAdd(&g_cellcnt[cid], 1);
}

// ---------------- K3: cell scan (shuffle-based) + fill cell-ordered arrays ----------------
__global__ void k_cell() {
    __shared__ int wsum[32];
    __shared__ int sfill[NCELL];
    int t = threadIdx.x;
    int a = (2 * t < NCELL) ? g_cellcnt[2 * t] : 0;
    int b = (2 * t + 1 < NCELL) ? g_cellcnt[2 * t + 1] : 0;
    int local = a + b;

    int v = local;
#pragma unroll
    for (int o = 1; o < 32; o <<= 1) {
        int u = __shfl_up_sync(0xFFFFFFFFu, v, o);
        if ((t & 31) >= o) v += u;
    }
    if ((t & 31) == 31) wsum[t >> 5] = v;
    __syncthreads();
    if (t < 32) {
        int w = wsum[t];
#pragma unroll
        for (int o = 1; o < 32; o <<= 1) {
            int u = __shfl_up_sync(0xFFFFFFFFu, w, o);
            if (t >= o) w += u;
        }
        wsum[t] = w;
    }
    __syncthreads();
    int incl = v + ((t >= 32) ? wsum[(t >> 5) - 1] : 0);
    int run = incl - local;
    if (2 * t < NCELL)     { sfill[2 * t] = run;         g_celloff[2 * t] = run; }
    if (2 * t + 1 < NCELL) { sfill[2 * t + 1] = run + a; g_celloff[2 * t + 1] = run + a; }
    if (t == 1023) g_celloff[NCELL] = incl;
    __syncthreads();
    for (int c = t; c < N; c += 1024) {
        int cid = g_cellid[c];
        int pos = atomicAdd(&sfill[cid], 1);
        g_crank[pos] = c;
        g_cfilt[pos] = g_filt[c];
    }
}

// ---------------- K4: edge extraction, one BLOCK per cell, shared staging ----------------
// Coverage proof: DIoU>=0.7 => per-dim |dc| <= 0.6*min(halfwidth) <= 13.2 < 16,
// so the 27-cell neighborhood of j's cell contains every qualifying partner.
// Each block stages its cell's j-boxes and the neighborhood candidates in shared,
// then pair-tests thread=candidate x loop-over-j with full lane utilization.
__global__ void k_edges() {
    int cid = blockIdx.x;
    int tid = threadIdx.x;

    __shared__ int ownS, ownE;
    __shared__ int spanS[9];
    __shared__ int spanP[10];
    __shared__ float4 jbf[JCAP], jA[JCAP], jB[JCAP];
    __shared__ int jrank[JCAP];
    __shared__ float4 cf[CCAP];
    __shared__ int cr[CCAP];

    if (tid == 0) { ownS = g_celloff[cid]; ownE = g_celloff[cid + 1]; }
    __syncthreads();
    int K0 = ownE - ownS;
    if (K0 <= 0) return;

    int ix = cid % GC, iy = (cid / GC) % GC, iz = cid / (GC * GC);
    int xlo = max(0, ix - 1), xhi = min(GC - 1, ix + 1);
    int ylo = max(0, iy - 1), yhi = min(GC - 1, iy + 1);
    int zlo = max(0, iz - 1), zhi = min(GC - 1, iz + 1);
    int ny = yhi - ylo + 1, nz = zhi - zlo + 1;
    int nspan = ny * nz;

    // parallel span fetch (<=9 spans, x-range collapsed to one contiguous run)
    if (tid < nspan) {
        int zz = zlo + tid / ny;
        int yy = ylo + tid % ny;
        int rb = (zz * GC + yy) * GC;
        spanS[tid] = g_celloff[rb + xlo];
        spanP[tid] = g_celloff[rb + xhi + 1] - g_celloff[rb + xlo];  // temp: length
    }
    __syncthreads();
    if (tid == 0) {
        int acc = 0;
        for (int s = 0; s < nspan; s++) {
            int len = spanP[s];
            spanP[s] = acc;
            acc += len;
        }
        for (int s = nspan; s < 9; s++) { spanS[s] = 0; spanP[s] = acc; }
        spanP[9] = acc;
    }
    __syncthreads();
    int T = spanP[9];

    for (int jbase = 0; jbase < K0; jbase += JCAP) {
        int K = min(JCAP, K0 - jbase);
        if (tid < K) {
            int p = ownS + jbase + tid;
            jbf[tid] = g_cfilt[p];
            int r = g_crank[p];
            jrank[tid] = r;
            jA[tid] = g_boxA[r];
            jB[tid] = g_boxB[r];
        }
        __syncthreads();

        for (int c0 = 0; c0 < T; c0 += CCAP) {
            int M = min(CCAP, T - c0);
            if (tid < M) {
                int g = c0 + tid;
                int s = 0;
                while (g >= spanP[s + 1]) s++;     // <=9 steps
                int p = spanS[s] + (g - spanP[s]);
                cf[tid] = g_cfilt[p];
                cr[tid] = g_crank[p];
            }
            __syncthreads();
            if (tid < M) {
                float4 f = cf[tid];
                int i = cr[tid];
                for (int jj = 0; jj < K; jj++) {
                    int j = jrank[jj];
                    if (i >= j) continue;
                    float4 bfj = jbf[jj];
                    float dx = bfj.x - f.x, dy = bfj.y - f.y, dz2 = bfj.z - f.z;
                    float d2 = dx * dx + dy * dy + dz2 * dz2;
                    if (d2 > fminf(f.w, bfj.w)) continue;

                    float4 Ai = g_boxA[i];
                    float4 Bi = g_boxB[i];
                    float4 A = jA[jj];
                    float4 B = jB[jj];
                    float iw = fminf(Ai.z, A.z) - fmaxf(Ai.x, A.x);
                    float ih = fminf(Ai.w, A.w) - fmaxf(Ai.y, A.y);
                    float dp = fminf(Bi.y, B.y) - fmaxf(Bi.x, B.x);
                    if (iw > 0.0f && ih > 0.0f && dp > 0.0f) {
                        float inter = iw * ih * dp;
                        float uni = Bi.z + B.z - inter + 1e-7f;
                        float ow = fmaxf(Ai.z, A.z) - fminf(Ai.x, A.x);
                        float oh = fmaxf(Ai.w, A.w) - fminf(Ai.y, A.y);
                        float od = fmaxf(Bi.y, B.y) - fminf(Bi.x, B.x);
                        float odiag = ow * ow + oh * oh + od * od + 1e-7f;
                        float v = inter / uni - d2 / odiag;
                        if (v >= NMS_TH) {
                            int e2 = atomicAdd(&g_ecount, 1);
                            if (e2 < MAX_E) {
                                g_eij[e2] = ((unsigned)i << 16) | (unsigned)j;
                                g_ev[e2] = v;
                                atomicAdd(&g_rowcnt[i], 1);
                            }
                        }
                    }
                }
            }
            __syncthreads();
        }
        __syncthreads();
    }
}

// ---------------- K5: all-shared CSR build + sort + bitmask fixed-point (1 block) ----------------
__global__ void k_post() {
    extern __shared__ int dyn[];
    int*          srow  = dyn;                      // N+1 row offsets
    int*          sfil  = srow + (N + 1);           // N fill cursors
    int*          scj   = sfil + N;                 // SE_CAP csr j
    float*        scv   = (float*)(scj + SE_CAP);   // SE_CAP csr v
    unsigned int* smask = (unsigned int*)(scv + SE_CAP);
    unsigned int* ssup  = smask + NW;
    __shared__ int wsum[32];
    int t = threadIdx.x;

    // offsets: per-thread chunk of 6 rows, shuffle-based block scan
    int base = t * 6;
    int cnt6[6];
    int local = 0;
#pragma unroll
    for (int k = 0; k < 6; k++) {
        int idx = base + k;
        cnt6[k] = (idx < N) ? g_rowcnt[idx] : 0;
        local += cnt6[k];
    }
    int v = local;
#pragma unroll
    for (int o = 1; o < 32; o <<= 1) {
        int u = __shfl_up_sync(0xFFFFFFFFu, v, o);
        if ((t & 31) >= o) v += u;
    }
    if ((t & 31) == 31) wsum[t >> 5] = v;
    __syncthreads();
    if (t < 32) {
        int w = wsum[t];
#pragma unroll
        for (int o = 1; o < 32; o <<= 1) {
            int u = __shfl_up_sync(0xFFFFFFFFu, w, o);
            if (t >= o) w += u;
        }
        wsum[t] = w;
    }
    __syncthreads();
    int run = v - local + ((t >= 32) ? wsum[(t >> 5) - 1] : 0);
#pragma unroll
    for (int k = 0; k < 6; k++) {
        int idx = base + k;
        if (idx < N) {
            srow[idx] = run;
            sfil[idx] = run;
            g_rowoff[idx] = run;
            run += cnt6[k];
        }
    }
    if (t == 1023) { srow[N] = run; g_rowoff[N] = run; }
    if (t < NW) smask[t] = 0xFFFFFFFFu;
    __syncthreads();

    int E = g_ecount;
    if (E > MAX_E) E = MAX_E;

    if (E <= SE_CAP) {
        // ---- shared-memory CSR path ----
        for (int e = t; e < E; e += 1024) {
            unsigned p = g_eij[e];
            int i = p >> 16;
            int pos = atomicAdd(&sfil[i], 1);
            scj[pos] = (int)(p & 0xFFFF);
            scv[pos] = g_ev[e];
        }
        __syncthreads();

        // per-row insertion sort by j in shared (determinism)
        for (int i = t; i < N; i += 1024) {
            int s0 = srow[i], s1 = srow[i + 1];
            for (int a = s0 + 1; a < s1; a++) {
                int jv = scj[a]; float vv = scv[a];
                int b = a - 1;
                while (b >= s0 && scj[b] > jv) {
                    scj[b + 1] = scj[b];
                    scv[b + 1] = scv[b];
                    b--;
                }
                scj[b + 1] = jv;
                scv[b + 1] = vv;
            }
        }
        __syncthreads();

        // bitmask fixed-point over shared CSR rows
        for (int it = 0; it < 200; it++) {
            if (t < NW) ssup[t] = 0u;
            __syncthreads();
#pragma unroll
            for (int k = 0; k < 6; k++) {
                int i = base + k;
                if (i < N && (smask[i >> 5] & (1u << (i & 31)))) {
                    int s0 = srow[i], s1 = srow[i + 1];
                    for (int e = s0; e < s1; e++) {
                        int j = scj[e];
                        atomicOr(&ssup[j >> 5], 1u << (j & 31));
                    }
                }
            }
            __syncthreads();
            int change = 0;
            if (t < NW) {
                unsigned nm = ~ssup[t];      // tail bits: never suppressed, stay 1
                if (nm != smask[t]) change = 1;
                smask[t] = nm;
            }
            if (!__syncthreads_or(change)) break;
        }
        // copy sorted CSR out for k_final
        for (int e = t; e < E; e += 1024) {
            g_csrj[e] = scj[e];
            g_csrv[e] = scv[e];
        }
    } else {
        // ---- global fallback path ----
        for (int i = t; i < N; i += 1024) g_fill[i] = srow[i];
        __syncthreads();
        for (int e = t; e < E; e += 1024) {
            unsigned p = g_eij[e];
            int i = p >> 16;
            int pos = atomicAdd(&g_fill[i], 1);
            g_csrj[pos] = (int)(p & 0xFFFF);
            g_csrv[pos] = g_ev[e];
        }
        __syncthreads();
        for (int i = t; i < N; i += 1024) {
            int s0 = srow[i], s1 = srow[i + 1];
            for (int a = s0 + 1; a < s1; a++) {
                int jv = g_csrj[a]; float vv = g_csrv[a];
                int b = a - 1;
                while (b >= s0 && g_csrj[b] > jv) {
                    g_csrj[b + 1] = g_csrj[b];
                    g_csrv[b + 1] = g_csrv[b];
                    b--;
                }
                g_csrj[b + 1] = jv;
                g_csrv[b + 1] = vv;
            }
        }
        __syncthreads();
        for (int it = 0; it < 200; it++) {
            if (t < NW) ssup[t] = 0u;
            __syncthreads();
            for (int e = t; e < E; e += 1024) {
                unsigned p = g_eij[e];
                int i = p >> 16, j = p & 0xFFFF;
                if (smask[i >> 5] & (1u << (i & 31)))
                    atomicOr(&ssup[j >> 5], 1u << (j & 31));
            }
            __syncthreads();
            int change = 0;
            if (t < NW) {
                unsigned nm = ~ssup[t];
                if (nm != smask[t]) change = 1;
                smask[t] = nm;
            }
            if (!__syncthreads_or(change)) break;
        }
    }
    if (t < NW) g_maskw[t] = smask[t];
}

// ---------------- K6: merge from CSR + write outputs (multi-block) ----------------
__global__ void k_final(float* __restrict__ out) {
    int i = blockIdx.x * 256 + threadIdx.x;
    if (i >= N) return;
    float4 Ai = g_boxA[i];
    float4 Bi = g_boxB[i];
    float s = Bi.w;
    float a0 = s * Ai.x, a1 = s * Ai.y, a2 = s * Ai.z;
    float a3 = s * Ai.w, a4 = s * Bi.x, a5 = s * Bi.y;
    float w = s;
    unsigned m = (g_maskw[i >> 5] >> (i & 31)) & 1u;
    if (m) {
        int s0 = g_rowoff[i], s1 = g_rowoff[i + 1];
        for (int e = s0; e < s1; e++) {
            float v = g_csrv[e];
            if (v > NMS_TH) {           // strict > for merge weights
                int j = g_csrj[e];
                float4 Aj = g_boxA[j];
                float4 Bj = g_boxB[j];
                float wt = v * Bj.w;
                w += wt;
                a0 += wt * Aj.x; a1 += wt * Aj.y; a2 += wt * Aj.z;
                a3 += wt * Aj.w; a4 += wt * Bj.x; a5 += wt * Bj.y;
            }
        }
    }
    float inv = 1.0f / w;
    out[i * 6 + 0] = a0 * inv; out[i * 6 + 1] = a1 * inv;
    out[i * 6 + 2] = a2 * inv; out[i * 6 + 3] = a3 * inv;
    out[i * 6 + 4] = a4 * inv; out[i * 6 + 5] = a5 * inv;
    out[N * 6 + i] = m ? 1.0f : 0.0f;
    out[N * 7 + i] = s;
}

// ---------------- launch ----------------
extern "C" void kernel_launch(void* const* d_in, const int* in_sizes, int n_in,
                              void* d_out, int out_size) {
    const float* boxes = (const float*)d_in[0];
    const float* scores = (const float*)d_in[1];
    float* out = (float*)d_out;

    const int post_smem = POST_SMEM_INTS * 4;   // ~114 KB dynamic shared
    cudaFuncSetAttribute(k_post, cudaFuncAttributeMaxDynamicSharedMemorySize, post_smem);

    k_rank<<<dim3(12, NCHUNK), 256>>>(scores);
    k_scatter<<<24, 256>>>(boxes, scores);
    k_cell<<<1, 1024>>>();
    k_edges<<<NCELL, CCAP>>>();
    k_post<<<1, 1024, post_smem>>>();
    k_final<<<24, 256>>>(out);
}